// round 4
// baseline (speedup 1.0000x reference)
#include <cuda_runtime.h>
#include <cstdint>

// SampleQueryExtractionLayer: 4-tap gather via cp.async.bulk pipeline.
// features: [B=4, N=4096, C=256] fp32, query_points: [4,8,256,2] -> 8192 queries
// out: [8192, 256] fp32.
//
// Per query the 4 taps are rows {n00, n00+1} and {n00+64, n00+65} of the
// [4096,256] feature matrix -> two contiguous 2KB segments. Each block owns
// 16 queries and streams them through an 8-deep smem pipeline filled by
// cp.async.bulk (UBLKCP) with mbarrier completion; 256 threads consume one
// query per stage (1 channel/thread).

#define EPS_F 0.0001f
#define QPB   16      // queries per block
#define DEPTH 8       // pipeline stages
#define NTHR  256

__device__ __forceinline__ uint32_t smem_u32(const void* p) {
    return (uint32_t)__cvta_generic_to_shared(p);
}

__device__ __forceinline__ void mbar_init(uint32_t a, uint32_t cnt) {
    asm volatile("mbarrier.init.shared.b64 [%0], %1;" :: "r"(a), "r"(cnt) : "memory");
}

__device__ __forceinline__ void mbar_expect_tx(uint32_t a, uint32_t bytes) {
    asm volatile("mbarrier.arrive.expect_tx.shared.b64 _, [%0], %1;"
                 :: "r"(a), "r"(bytes) : "memory");
}

__device__ __forceinline__ void mbar_wait(uint32_t mbar, uint32_t parity) {
    asm volatile(
        "{\n\t"
        ".reg .pred P;\n\t"
        "WAIT_%=:\n\t"
        "mbarrier.try_wait.parity.acquire.cta.shared::cta.b64 P, [%0], %1, 0x989680;\n\t"
        "@P bra.uni DONE_%=;\n\t"
        "bra.uni WAIT_%=;\n\t"
        "DONE_%=:\n\t"
        "}"
        :: "r"(mbar), "r"(parity) : "memory");
}

__device__ __forceinline__ void bulk_g2s(uint32_t dst, const float* src,
                                         uint32_t bytes, uint32_t mbar) {
    asm volatile(
        "cp.async.bulk.shared::cta.global.mbarrier::complete_tx::bytes [%0], [%1], %2, [%3];"
        :: "r"(dst), "l"(src), "r"(bytes), "r"(mbar) : "memory");
}

__global__ __launch_bounds__(NTHR)
void sqe_kernel(const float* __restrict__ feat,
                const float* __restrict__ qp,
                float* __restrict__ out)
{
    __shared__ __align__(16) float stage[DEPTH][1024];   // 4KB per stage = 4 rows
    __shared__ float s_w[QPB][4];                        // normalized corner weights
    __shared__ int   s_off[QPB];                         // float offset of row n00
    __shared__ __align__(8) unsigned long long s_mbar[DEPTH];

    const int tid   = threadIdx.x;
    const int qbase = blockIdx.x * QPB;

    if (tid < DEPTH) mbar_init(smem_u32(&s_mbar[tid]), 1);

    // Precompute all 16 queries' weights + gather offsets (one thread each).
    if (tid < QPB) {
        const int g = qbase + tid;
        const float2 p = __ldg(((const float2*)qp) + g);
        const int y0 = __float2int_rd(p.x);
        const int x0 = __float2int_rd(p.y);
        const float dy = p.x - (float)y0;
        const float dx = p.y - (float)x0;
        const float m00 = fmaxf(0.f, 1.f - (dy + dx)        + EPS_F);
        const float m01 = fmaxf(0.f, 1.f - (dy + 1.f - dx)  + EPS_F);
        const float m10 = fmaxf(0.f, 1.f - (1.f - dy + dx)  + EPS_F);
        const float m11 = fmaxf(0.f, 1.f - (2.f - dy - dx)  + EPS_F);
        float w00 = m00 * m00, w01 = m01 * m01, w10 = m10 * m10, w11 = m11 * m11;
        const float inv = __fdividef(1.f, w00 + w01 + w10 + w11 + EPS_F);
        s_w[tid][0] = w00 * inv;
        s_w[tid][1] = w01 * inv;
        s_w[tid][2] = w10 * inv;
        s_w[tid][3] = w11 * inv;
        const int b = g >> 11;                        // 2048 queries per batch
        s_off[tid] = (b * 4096 + y0 * 64 + x0) * 256; // row n00 in floats
    }
    __syncthreads();

    // Prologue: fill all DEPTH stages.
    if (tid == 0) {
        #pragma unroll
        for (int j = 0; j < DEPTH; ++j) {
            const uint32_t mb = smem_u32(&s_mbar[j]);
            mbar_expect_tx(mb, 4096);
            const float* src = feat + s_off[j];
            bulk_g2s(smem_u32(&stage[j][0]),   src,            2048, mb); // rows n00, n00+1
            bulk_g2s(smem_u32(&stage[j][512]), src + 64 * 256, 2048, mb); // rows n00+64, n00+65
        }
    }

    // Mainloop: consume stage i, refill with query i+DEPTH.
    for (int i = 0; i < QPB; ++i) {
        const int s = i & (DEPTH - 1);
        mbar_wait(smem_u32(&s_mbar[s]), (i / DEPTH) & 1);

        const float w0 = s_w[i][0], w1 = s_w[i][1], w2 = s_w[i][2], w3 = s_w[i][3];
        const float f0 = stage[s][tid];
        const float f1 = stage[s][256 + tid];
        const float f2 = stage[s][512 + tid];
        const float f3 = stage[s][768 + tid];
        out[(size_t)(qbase + i) * 256 + tid] = w0 * f0 + w1 * f1 + w2 * f2 + w3 * f3;

        __syncthreads();   // all threads done with slot s
        if (tid == 0 && i + DEPTH < QPB) {
            asm volatile("fence.proxy.async.shared::cta;" ::: "memory");
            const uint32_t mb = smem_u32(&s_mbar[s]);
            mbar_expect_tx(mb, 4096);
            const float* src = feat + s_off[i + DEPTH];
            bulk_g2s(smem_u32(&stage[s][0]),   src,            2048, mb);
            bulk_g2s(smem_u32(&stage[s][512]), src + 64 * 256, 2048, mb);
        }
    }
}

extern "C" void kernel_launch(void* const* d_in, const int* in_sizes, int n_in,
                              void* d_out, int out_size)
{
    (void)in_sizes; (void)n_in; (void)out_size;
    const float* feat = (const float*)d_in[0];
    const float* qp   = (const float*)d_in[1];
    float* out        = (float*)d_out;

    // 8192 queries / 16 per block = 512 blocks
    sqe_kernel<<<512, NTHR>>>(feat, qp, out);
}

// round 5
// speedup vs baseline: 1.2060x; 1.2060x over previous
#include <cuda_runtime.h>

// SampleQueryExtractionLayer: bilinear-style 4-tap gather.
// features: [B=4, N=4096, C=256] fp32   (d_in[0])
// query_points: [B=4, S=8, Q=256, 2] fp32 (d_in[1]) -> 8192 points
// out: [B, S, Q, C] fp32 = [8192, 256]
//
// Single-wave layout: 2048 blocks x 128 threads; each 64-thread group owns
// TWO queries (grp and grp+4096), processed sequentially so the gather
// registers are reused. Both query-point loads are issued up front, so the
// dependent qp->address hop is paid once per thread.

#define EPS_F 0.0001f

__device__ __forceinline__ void do_query(const float* __restrict__ feat,
                                         float* __restrict__ out,
                                         float2 p, int g, int c4)
{
    const int y0 = __float2int_rd(p.x);
    const int x0 = __float2int_rd(p.y);
    const int b  = g >> 11;                      // 2048 queries per batch

    const float4* r00 = (const float4*)feat
                        + (size_t)(b * 4096 + y0 * 64 + x0) * 64 + c4;
    // 4 independent gathers, front-batched.
    const float4 f00 = __ldg(r00);
    const float4 f01 = __ldg(r00 + 64);          // (y0, x0+1)
    const float4 f10 = __ldg(r00 + 64 * 64);     // (y0+1, x0)
    const float4 f11 = __ldg(r00 + 64 * 65);     // (y0+1, x0+1)

    // Weight math overlaps the gather latency.
    const float dy = p.x - (float)y0;
    const float dx = p.y - (float)x0;
    const float m00 = fmaxf(0.f, 1.f - (dy + dx)       + EPS_F);
    const float m01 = fmaxf(0.f, 1.f - (dy + 1.f - dx) + EPS_F);
    const float m10 = fmaxf(0.f, 1.f - (1.f - dy + dx) + EPS_F);
    const float m11 = fmaxf(0.f, 1.f - (2.f - dy - dx) + EPS_F);
    const float w00 = m00 * m00;
    const float w01 = m01 * m01;
    const float w10 = m10 * m10;
    const float w11 = m11 * m11;
    const float inv = __fdividef(1.f, w00 + w01 + w10 + w11 + EPS_F);

    float4 acc;
    acc.x = (w00*f00.x + w01*f01.x + w10*f10.x + w11*f11.x) * inv;
    acc.y = (w00*f00.y + w01*f01.y + w10*f10.y + w11*f11.y) * inv;
    acc.z = (w00*f00.z + w01*f01.z + w10*f10.z + w11*f11.z) * inv;
    acc.w = (w00*f00.w + w01*f01.w + w10*f10.w + w11*f11.w) * inv;

    // Evict-first store: keep the feature matrix resident in L2.
    __stcs(((float4*)out) + (size_t)g * 64 + c4, acc);
}

__global__ __launch_bounds__(128)
void sqe_kernel(const float* __restrict__ feat,
                const float* __restrict__ qp,
                float* __restrict__ out)
{
    const int tid = threadIdx.x;
    const int grp = blockIdx.x * 2 + (tid >> 6);   // 0..4095
    const int c4  = tid & 63;

    const int q0 = grp;            // batches 0-1
    const int q1 = grp + 4096;     // batches 2-3

    // Both qp loads issue immediately (independent); one latency hop total.
    const float2 p0 = __ldg(((const float2*)qp) + q0);
    const float2 p1 = __ldg(((const float2*)qp) + q1);

    do_query(feat, out, p0, q0, c4);
    do_query(feat, out, p1, q1, c4);
}

extern "C" void kernel_launch(void* const* d_in, const int* in_sizes, int n_in,
                              void* d_out, int out_size)
{
    (void)in_sizes; (void)n_in; (void)out_size;
    const float* feat = (const float*)d_in[0];
    const float* qp   = (const float*)d_in[1];
    float* out        = (float*)d_out;

    // 4096 query-groups, 2 groups per 128-thread block -> 2048 blocks,
    // 2 queries per group -> all 8192 queries in a single wave.
    sqe_kernel<<<2048, 128>>>(feat, qp, out);
}